// round 17
// baseline (speedup 1.0000x reference)
#include <cuda_runtime.h>
#include <cuda_bf16.h>
#include <cuda_fp16.h>
#include <cstdint>

#define F_IN  512
#define HID   16
#define C_OUT 40
#define MAXN  100000
#define MAXE  3200000
#define SCAN_BLK 1024
#define MAXSB 128
#define PERSIST_BLOCKS 1184

typedef unsigned long long ull;
typedef unsigned int u32;

// ---------------- scratch (static device globals, no allocs) ----------------
// g_deg zero-initialized at load; k_gemm2 re-zeros each call (graph-replay safe).
__device__ __align__(128) int    g_deg [MAXN];
__device__ __align__(128) int    g_rp  [MAXN];   // CSR row ptr
__device__ __align__(128) int    g_rpc [MAXN];   // working copy for fill
__device__ __align__(128) int    g_bsum[MAXSB];
__device__ __align__(128) int    g_csr [MAXE];
__device__ __align__(128) __half g_B1h [MAXN * HID];  // fp16 message buffer
__device__ __align__(128) float  g_B2  [MAXN * HID];  // fp32 accum (self + agg)
__device__ __align__(128) float  g_W1h [F_IN * HID];
__device__ __align__(128) float  g_W1l [F_IN * HID];

// ---------------- helpers ----------------
__device__ __forceinline__ u32 s2u(const void* p) {
    u32 a;
    asm("{ .reg .u64 t; cvta.to.shared.u64 t, %1; cvt.u32.u64 %0, t; }"
        : "=r"(a) : "l"(p));
    return a;
}
__device__ __forceinline__ void cpa16(u32 dst, const void* src, int sz) {
    asm volatile("cp.async.cg.shared.global [%0], [%1], 16, %2;"
                 :: "r"(dst), "l"(src), "r"(sz) : "memory");
}
__device__ __forceinline__ void cpa_commit() {
    asm volatile("cp.async.commit_group;" ::: "memory");
}
template <int NN>
__device__ __forceinline__ void cpa_wait() {
    asm volatile("cp.async.wait_group %0;" :: "n"(NN) : "memory");
}
__device__ __forceinline__ u32 tf32_of(float f) {
    u32 r;
    asm("cvt.rna.tf32.f32 %0, %1;" : "=r"(r) : "f"(f));
    return r;
}
__device__ __forceinline__ void tf32_split(float a, u32& hi, u32& lo) {
    hi = tf32_of(a);
    lo = tf32_of(a - __uint_as_float(hi));
}
__device__ __forceinline__ void mma_tf32(float& d0, float& d1, float& d2, float& d3,
                                         u32 a0, u32 a1, u32 a2, u32 a3,
                                         u32 b0, u32 b1) {
    asm("mma.sync.aligned.m16n8k8.row.col.f32.tf32.tf32.f32 "
        "{%0,%1,%2,%3}, {%4,%5,%6,%7}, {%8,%9}, {%0,%1,%2,%3};"
        : "+f"(d0), "+f"(d1), "+f"(d2), "+f"(d3)
        : "r"(a0), "r"(a1), "r"(a2), "r"(a3), "r"(b0), "r"(b1));
}

// ----- launch 0: degree histogram + W1 tf32 split, persistent ---------------
__global__ __launch_bounds__(256) void k_hist_ws(const int* __restrict__ dst, int* deg,
                                                 const float* __restrict__ W1,
                                                 float* wh, float* wl, int E, int nw) {
    const int tid0   = blockIdx.x * blockDim.x + threadIdx.x;
    const int stride = gridDim.x * blockDim.x;
    for (int i = tid0; i < nw; i += stride) {
        float w = W1[i];
        u32 h, l;
        tf32_split(w, h, l);
        wh[i] = __uint_as_float(h);
        wl[i] = __uint_as_float(l);
    }
#pragma unroll 4
    for (int i = tid0; i < E; i += stride)
        atomicAdd(&deg[__ldg(&dst[i])], 1);
}

// ---------------- scan (exclusive prefix of deg -> rp) ----------------------
__global__ __launch_bounds__(256) void k_scan1(const int* __restrict__ deg,
                                               int* rp, int* bsum, int N) {
    __shared__ int sd[256];
    int t = threadIdx.x;
    int base = blockIdx.x * SCAN_BLK + t * 4;
    int4 v = make_int4(0, 0, 0, 0);
    if (base + 3 < N) v = *(const int4*)&deg[base];
    else {
        if (base + 0 < N) v.x = deg[base + 0];
        if (base + 1 < N) v.y = deg[base + 1];
        if (base + 2 < N) v.z = deg[base + 2];
    }
    sd[t] = v.x + v.y + v.z + v.w;
    __syncthreads();
    for (int off = 1; off < 256; off <<= 1) {
        int val = sd[t];
        int add = (t >= off) ? sd[t - off] : 0;
        __syncthreads();
        sd[t] = val + add;
        __syncthreads();
    }
    int excl = (t == 0) ? 0 : sd[t - 1];
    if (t == 255) bsum[blockIdx.x] = sd[255];
    if (base + 0 < N) rp[base + 0] = excl;
    if (base + 1 < N) rp[base + 1] = excl + v.x;
    if (base + 2 < N) rp[base + 2] = excl + v.x + v.y;
    if (base + 3 < N) rp[base + 3] = excl + v.x + v.y + v.z;
}
__global__ __launch_bounds__(MAXSB) void k_scan2(int* bsum, int nb) {
    __shared__ int sd[MAXSB];
    int t = threadIdx.x;
    sd[t] = (t < nb) ? bsum[t] : 0;
    __syncthreads();
    for (int off = 1; off < MAXSB; off <<= 1) {
        int val = sd[t];
        int add = (t >= off) ? sd[t - off] : 0;
        __syncthreads();
        sd[t] = val + add;
        __syncthreads();
    }
    if (t < nb) bsum[t] = (t == 0) ? 0 : sd[t - 1];
}
__global__ void k_scan3(int* rp, int* rpc, const int* __restrict__ bsum, int N) {
    int i = blockIdx.x * blockDim.x + threadIdx.x;
    if (i < N) {
        int v = rp[i] + bsum[i / SCAN_BLK];
        rp[i]  = v;
        rpc[i] = v;
    }
}
// fill: csr[pos] = src for each edge
__global__ void k_fill(const int* __restrict__ src, const int* __restrict__ dst,
                       int* rpc, int* csr, int E) {
    int i = blockIdx.x * blockDim.x + threadIdx.x;
    if (i < E) {
        int pos = atomicAdd(&rpc[__ldg(&dst[i])], 1);
        csr[pos] = __ldg(&src[i]);
    }
}

// ------ GEMM1 v9: tf32 mma 2-term, 3-stage cp.async pipeline ----------------
#define G1_NS 3
#define G1_XS 20
#define G1_WS 24
#define G1_XSZ (128 * G1_XS)
#define G1_WSZ (16 * G1_WS)
__global__ __launch_bounds__(256) void k_gemm1(const float* __restrict__ x,
                                               const float* __restrict__ W1h,
                                               const float* __restrict__ W1l,
                                               const int* __restrict__ deg,
                                               __half* __restrict__ h0h,
                                               float* __restrict__ h1, int N) {
    __shared__ __align__(16) float xs3[G1_NS][G1_XSZ];
    __shared__ __align__(16) float wh3[G1_NS][G1_WSZ];
    __shared__ __align__(16) float wl3[G1_NS][G1_WSZ];
    const int t    = threadIdx.x;
    const int lane = t & 31;
    const int wid  = t >> 5;
    const int gid  = lane >> 2;
    const int tig  = lane & 3;
    const int base = blockIdx.x * 128;

    u32 xoff[2];
    const float* xsrc[2];
    int xsz[2];
#pragma unroll
    for (int j = 0; j < 2; j++) {
        int idx = t + 256 * j;
        int r = idx >> 2, q = idx & 3;
        xoff[j] = r * G1_XS + q * 4;
        xsrc[j] = x + (size_t)(base + r) * F_IN + q * 4;
        xsz[j]  = (base + r < N) ? 16 : 0;
    }
    const int wc = t & 63;
    const int wkk = wc >> 2, wq = wc & 3;
    const u32 woff = wkk * G1_WS + wq * 4;
    const float* wsrcb = ((t & 127) < 64 ? W1h : W1l) + (size_t)wkk * 16 + wq * 4;
    const bool do_w = (t < 128);
    const bool w_hi = (t < 64);

    float d0[4] = {0.f, 0.f, 0.f, 0.f};
    float d1[4] = {0.f, 0.f, 0.f, 0.f};

#pragma unroll
    for (int s = 0; s < G1_NS; s++) {
        const int kg = s * 16;
        if (do_w) {
            float* wbase = w_hi ? &wh3[s][0] : &wl3[s][0];
            cpa16(s2u(wbase) + woff * 4, wsrcb + (size_t)kg * 16, 16);
        }
#pragma unroll
        for (int j = 0; j < 2; j++)
            cpa16(s2u(&xs3[s][0]) + xoff[j] * 4, xsrc[j] + kg, xsz[j]);
        cpa_commit();
    }

    const int ra = wid * 16 + gid;
    for (int kt = 0; kt < 32; kt++) {
        const int buf = kt % G1_NS;
        cpa_wait<G1_NS - 1>();
        __syncthreads();

#pragma unroll
        for (int s = 0; s < 2; s++) {
            const int ko = s * 8;
            float a0 = xs3[buf][ra * G1_XS + ko + tig];
            float a1 = xs3[buf][(ra + 8) * G1_XS + ko + tig];
            float a2 = xs3[buf][ra * G1_XS + ko + tig + 4];
            float a3 = xs3[buf][(ra + 8) * G1_XS + ko + tig + 4];
            u32 a0h = tf32_of(a0), a1h = tf32_of(a1);
            u32 a2h = tf32_of(a2), a3h = tf32_of(a3);
            u32 b0h = __float_as_uint(wh3[buf][(ko + tig) * G1_WS + gid]);
            u32 b1h = __float_as_uint(wh3[buf][(ko + tig + 4) * G1_WS + gid]);
            u32 b2h = __float_as_uint(wh3[buf][(ko + tig) * G1_WS + gid + 8]);
            u32 b3h = __float_as_uint(wh3[buf][(ko + tig + 4) * G1_WS + gid + 8]);
            u32 b0l = __float_as_uint(wl3[buf][(ko + tig) * G1_WS + gid]);
            u32 b1l = __float_as_uint(wl3[buf][(ko + tig + 4) * G1_WS + gid]);
            u32 b2l = __float_as_uint(wl3[buf][(ko + tig) * G1_WS + gid + 8]);
            u32 b3l = __float_as_uint(wl3[buf][(ko + tig + 4) * G1_WS + gid + 8]);

            mma_tf32(d0[0], d0[1], d0[2], d0[3], a0h, a1h, a2h, a3h, b0h, b1h);
            mma_tf32(d1[0], d1[1], d1[2], d1[3], a0h, a1h, a2h, a3h, b2h, b3h);
            mma_tf32(d0[0], d0[1], d0[2], d0[3], a0h, a1h, a2h, a3h, b0l, b1l);
            mma_tf32(d1[0], d1[1], d1[2], d1[3], a0h, a1h, a2h, a3h, b2l, b3l);
        }
        __syncthreads();

        const int ktp = kt + G1_NS;
        if (ktp < 32) {
            const int kg = ktp * 16;
            if (do_w) {
                float* wbase = w_hi ? &wh3[buf][0] : &wl3[buf][0];
                cpa16(s2u(wbase) + woff * 4, wsrcb + (size_t)kg * 16, 16);
            }
#pragma unroll
            for (int j = 0; j < 2; j++)
                cpa16(s2u(&xs3[buf][0]) + xoff[j] * 4, xsrc[j] + kg, xsz[j]);
        }
        cpa_commit();
    }

    {
        int r0 = base + wid * 16 + gid;
        int r1 = r0 + 8;
        if (r0 < N) {
            float dv = rsqrtf((float)(deg[r0] + 1));
            float4 v = make_float4(d0[0] * dv, d0[1] * dv, d1[0] * dv, d1[1] * dv);
            *(__half2*)&h0h[(size_t)r0 * HID + 2 * tig]     = __floats2half2_rn(v.x, v.y);
            *(__half2*)&h0h[(size_t)r0 * HID + 8 + 2 * tig] = __floats2half2_rn(v.z, v.w);
            *(float2*)&h1[(size_t)r0 * HID + 2 * tig]     = make_float2(v.x, v.y);
            *(float2*)&h1[(size_t)r0 * HID + 8 + 2 * tig] = make_float2(v.z, v.w);
        }
        if (r1 < N) {
            float dv = rsqrtf((float)(deg[r1] + 1));
            float4 v = make_float4(d0[2] * dv, d0[3] * dv, d1[2] * dv, d1[3] * dv);
            *(__half2*)&h0h[(size_t)r1 * HID + 2 * tig]     = __floats2half2_rn(v.x, v.y);
            *(__half2*)&h0h[(size_t)r1 * HID + 8 + 2 * tig] = __floats2half2_rn(v.z, v.w);
            *(float2*)&h1[(size_t)r1 * HID + 2 * tig]     = make_float2(v.x, v.y);
            *(float2*)&h1[(size_t)r1 * HID + 8 + 2 * tig] = make_float2(v.z, v.w);
        }
    }
}

// --- CSR aggregation: warp/node, fp16 gather, in-place fp32 accum -----------
// io[d] holds the fp32 self-loop term on entry; on exit io[d] = self + sum.
__global__ __launch_bounds__(256) void k_agg_csr(const int* __restrict__ rp,
                                                 const int* __restrict__ deg,
                                                 const int* __restrict__ csr,
                                                 const __half* __restrict__ inh,
                                                 float* io, int N) {
    int gtid = blockIdx.x * blockDim.x + threadIdx.x;
    int d = gtid >> 5;
    if (d >= N) return;
    int lane = gtid & 31;
    int sub = lane >> 2;    // 0..7
    int c   = lane & 3;     // 0..3  (quarter of the 16-dim row)
    int beg = __ldg(&rp[d]);
    int cnt = __ldg(&deg[d]);
    float4 acc = make_float4(0.f, 0.f, 0.f, 0.f);
    for (int i = sub; i < cnt; i += 8) {
        int s = __ldg(&csr[beg + i]);
        uint2 v = __ldg((const uint2*)(inh + (size_t)s * HID) + c);
        float2 f0 = __half22float2(*(__half2*)&v.x);
        float2 f1 = __half22float2(*(__half2*)&v.y);
        acc.x += f0.x; acc.y += f0.y; acc.z += f1.x; acc.w += f1.y;
    }
#pragma unroll
    for (int off = 16; off >= 4; off >>= 1) {
        acc.x += __shfl_xor_sync(0xffffffffu, acc.x, off);
        acc.y += __shfl_xor_sync(0xffffffffu, acc.y, off);
        acc.z += __shfl_xor_sync(0xffffffffu, acc.z, off);
        acc.w += __shfl_xor_sync(0xffffffffu, acc.w, off);
    }
    if (sub == 0) {
        float4* p = (float4*)(io + (size_t)d * HID) + c;
        float4 self = *p;
        *p = make_float4(self.x + acc.x, self.y + acc.y,
                         self.z + acc.z, self.w + acc.w);
    }
}

// -------- a~ = dinv * relu(dinv * y1 + b1): fp16 -> o0h, fp32 -> o1 ---------
__global__ void k_relubias(const float4* __restrict__ in4, const int* __restrict__ deg,
                           const float* __restrict__ b1,
                           __half* __restrict__ o0h, float4* __restrict__ o1, int N) {
    int i = blockIdx.x * blockDim.x + threadIdx.x;
    if (i < N * (HID / 4)) {
        float dv = rsqrtf((float)(deg[i >> 2] + 1));
        int jb = (i & 3) * 4;
        float4 v = in4[i];
        v.x = fmaxf(fmaf(v.x, dv, b1[jb + 0]), 0.f) * dv;
        v.y = fmaxf(fmaf(v.y, dv, b1[jb + 1]), 0.f) * dv;
        v.z = fmaxf(fmaf(v.z, dv, b1[jb + 2]), 0.f) * dv;
        v.w = fmaxf(fmaf(v.w, dv, b1[jb + 3]), 0.f) * dv;
        __half2 ha = __floats2half2_rn(v.x, v.y);
        __half2 hb = __floats2half2_rn(v.z, v.w);
        *(uint2*)&o0h[(size_t)i * 4] = make_uint2(*(u32*)&ha, *(u32*)&hb);
        o1[i] = v;
    }
}

// ------- GEMM2 + b2; resets deg for next graph replay ----------------------
__global__ __launch_bounds__(128) void k_gemm2(const float* __restrict__ y2,
                                               int* deg,
                                               const float* __restrict__ W2,
                                               const float* __restrict__ b2,
                                               float* __restrict__ out, int N) {
    __shared__ float w2s[HID * C_OUT];
    __shared__ float b2s[C_OUT];
    int t = threadIdx.x;
    for (int i = t; i < HID * C_OUT; i += 128) w2s[i] = W2[i];
    if (t < C_OUT) b2s[t] = b2[t];
    __syncthreads();
    int i = blockIdx.x * 128 + t;
    if (i >= N) return;
    float dv = rsqrtf((float)(deg[i] + 1));
    deg[i] = 0;   // self-clean for next call
    float a[HID];
#pragma unroll
    for (int k4 = 0; k4 < 4; k4++) {
        float4 v = *(const float4*)&y2[(size_t)i * HID + 4 * k4];
        a[4 * k4 + 0] = v.x * dv; a[4 * k4 + 1] = v.y * dv;
        a[4 * k4 + 2] = v.z * dv; a[4 * k4 + 3] = v.w * dv;
    }
    float o[C_OUT];
#pragma unroll
    for (int j = 0; j < C_OUT; j++) o[j] = b2s[j];
#pragma unroll
    for (int k = 0; k < HID; k++) {
        float av = a[k];
#pragma unroll
        for (int j = 0; j < C_OUT; j++) o[j] += av * w2s[k * C_OUT + j];
    }
#pragma unroll
    for (int jg = 0; jg < C_OUT / 4; jg++) {
        float4 v = make_float4(o[4 * jg + 0], o[4 * jg + 1], o[4 * jg + 2], o[4 * jg + 3]);
        *(float4*)&out[(size_t)i * C_OUT + 4 * jg] = v;
    }
}

// ---------------- launcher ----------------
extern "C" void kernel_launch(void* const* d_in, const int* in_sizes, int n_in,
                              void* d_out, int out_size) {
    const float* x  = (const float*)d_in[0];
    const int*   ei = (const int*)d_in[1];
    const float* W1 = (const float*)d_in[2];
    const float* b1 = (const float*)d_in[3];
    const float* W2 = (const float*)d_in[4];
    const float* b2 = (const float*)d_in[5];
    float* out = (float*)d_out;

    const int N = in_sizes[0] / F_IN;
    const int E = in_sizes[1] / 2;
    const int* src = ei;
    const int* dst = ei + E;

    void *p;
    cudaGetSymbolAddress(&p, g_deg);  int*    deg  = (int*)p;
    cudaGetSymbolAddress(&p, g_rp);   int*    rp   = (int*)p;
    cudaGetSymbolAddress(&p, g_rpc);  int*    rpc  = (int*)p;
    cudaGetSymbolAddress(&p, g_bsum); int*    bsum = (int*)p;
    cudaGetSymbolAddress(&p, g_csr);  int*    csr  = (int*)p;
    cudaGetSymbolAddress(&p, g_B1h);  __half* B1h  = (__half*)p;
    cudaGetSymbolAddress(&p, g_B2);   float*  B2   = (float*)p;
    cudaGetSymbolAddress(&p, g_W1h);  float*  W1h  = (float*)p;
    cudaGetSymbolAddress(&p, g_W1l);  float*  W1l  = (float*)p;

    const int TB = 256;
    const int nv4 = N * (HID / 4);
    const int nb  = (N + SCAN_BLK - 1) / SCAN_BLK;

    // 0: degree histogram + W1 split
    k_hist_ws<<<PERSIST_BLOCKS, TB>>>(dst, deg, W1, W1h, W1l, E, F_IN * HID);
    // 1-3: scan -> rp, rpc
    k_scan1<<<nb, 256>>>(deg, rp, bsum, N);
    k_scan2<<<1, MAXSB>>>(bsum, nb);
    k_scan3<<<(N + TB - 1) / TB, TB>>>(rp, rpc, bsum, N);
    // 4: CSR fill
    k_fill<<<(E + TB - 1) / TB, TB>>>(src, dst, rpc, csr, E);
    // 5: h~ = dinv * (x @ W1) -> B1h (fp16 messages) and B2 (fp32 self term)
    k_gemm1<<<(N + 127) / 128, 256>>>(x, W1h, W1l, deg, B1h, B2, N);
    // 6: B2 = self + A * B1h  (CSR gather, no atomics)
    k_agg_csr<<<(N * 32 + TB - 1) / TB, TB>>>(rp, deg, csr, B1h, B2, N);
    // 7: a~ -> B1h and B2 (self term)
    k_relubias<<<(nv4 + TB - 1) / TB, TB>>>((const float4*)B2, deg, b1,
                                            B1h, (float4*)B2, N);
    // 8: B2 = self + A * B1h
    k_agg_csr<<<(N * 32 + TB - 1) / TB, TB>>>(rp, deg, csr, B1h, B2, N);
    // 9: out = (dinv * B2) @ W2 + b2 ; deg reset
    k_gemm2<<<(N + 127) / 128, 128>>>(B2, deg, W2, b2, out, N);
}